// round 1
// baseline (speedup 1.0000x reference)
#include <cuda_runtime.h>
#include <cstdint>
#include <cstddef>

// Problem constants
#define B_   2
#define L_   2048
#define D_   1024
#define H_   16
#define HD_  64
#define TOK  (B_ * L_)          // 4096 tokens

// ---------------------------------------------------------------------------
// Scratch (no cudaMalloc allowed) — __device__ globals
// ---------------------------------------------------------------------------
__device__ float g_qkv[(size_t)TOK * 3 * D_];   // [tok, 3D] interleaved q|k|v
__device__ float g_ctx[(size_t)TOK * D_];       // [tok, D] attention context

// ---------------------------------------------------------------------------
// SGEMM:  C[M,N] = A[M,K] * B[N,K]^T      (both A and B are K-major row-major)
// 128x128 tile, BK=8, 8x8 per thread, 256 threads, register prefetch.
// M,N,K are multiples of the tile sizes for all calls here (no bounds checks).
// ---------------------------------------------------------------------------
#define BM  128
#define BN  128
#define BKK 8

__global__ void __launch_bounds__(256) sgemm_nt(
    const float* __restrict__ A, const float* __restrict__ Bm,
    float* __restrict__ C, int M, int N, int K)
{
    __shared__ __align__(16) float As[BKK][BM + 4];
    __shared__ __align__(16) float Bs[BKK][BN + 4];

    const int tid = threadIdx.x;
    const int tx  = tid & 15;        // 16 col-groups
    const int ty  = tid >> 4;        // 16 row-groups
    const int bm  = blockIdx.y * BM;
    const int bn  = blockIdx.x * BN;

    // Global-load mapping: each thread loads one float4 of A and one of B per tile
    const int lrow = tid >> 1;           // 0..127
    const int lcol = (tid & 1) * 4;      // 0 or 4
    const float* Ap = A  + (size_t)(bm + lrow) * K + lcol;
    const float* Bp = Bm + (size_t)(bn + lrow) * K + lcol;

    float acc[8][8];
    #pragma unroll
    for (int i = 0; i < 8; i++)
        #pragma unroll
        for (int j = 0; j < 8; j++) acc[i][j] = 0.0f;

    float4 a_n = *(const float4*)(Ap);
    float4 b_n = *(const float4*)(Bp);

    for (int k0 = 0; k0 < K; k0 += BKK) {
        // store current tile (transposed) to smem
        As[lcol + 0][lrow] = a_n.x;
        As[lcol + 1][lrow] = a_n.y;
        As[lcol + 2][lrow] = a_n.z;
        As[lcol + 3][lrow] = a_n.w;
        Bs[lcol + 0][lrow] = b_n.x;
        Bs[lcol + 1][lrow] = b_n.y;
        Bs[lcol + 2][lrow] = b_n.z;
        Bs[lcol + 3][lrow] = b_n.w;
        __syncthreads();

        // prefetch next tile into registers (hides global latency under compute)
        if (k0 + BKK < K) {
            a_n = *(const float4*)(Ap + k0 + BKK);
            b_n = *(const float4*)(Bp + k0 + BKK);
        }

        #pragma unroll
        for (int kk = 0; kk < BKK; kk++) {
            float a[8], b[8];
            *(float4*)&a[0] = *(const float4*)&As[kk][ty * 8];
            *(float4*)&a[4] = *(const float4*)&As[kk][ty * 8 + 4];
            *(float4*)&b[0] = *(const float4*)&Bs[kk][tx * 8];
            *(float4*)&b[4] = *(const float4*)&Bs[kk][tx * 8 + 4];
            #pragma unroll
            for (int i = 0; i < 8; i++)
                #pragma unroll
                for (int j = 0; j < 8; j++)
                    acc[i][j] = fmaf(a[i], b[j], acc[i][j]);
        }
        __syncthreads();
    }

    #pragma unroll
    for (int i = 0; i < 8; i++) {
        float* Cp = C + (size_t)(bm + ty * 8 + i) * N + bn + tx * 8;
        float4 o0 = make_float4(acc[i][0], acc[i][1], acc[i][2], acc[i][3]);
        float4 o1 = make_float4(acc[i][4], acc[i][5], acc[i][6], acc[i][7]);
        *(float4*)(Cp)     = o0;
        *(float4*)(Cp + 4) = o1;
    }
}

// ---------------------------------------------------------------------------
// Fused causal flash-attention.
// One block = (batch*head, 64-row Q tile). 256 threads = 16x16 grid, each
// thread owns a 4x4 subtile of the 64x64 S / O tiles. Online softmax state
// (m, l) is held per-row in registers, replicated across the 16 column-lanes
// of each row (all 16 lanes of a row group live in one warp -> shfl butterfly).
// ---------------------------------------------------------------------------
#define TQ 64
#define SSTR 68                      // padded smem row stride (floats)
#define QS_OFF 0
#define KT_OFF (64 * SSTR)
#define VS_OFF (2 * 64 * SSTR)
#define PS_OFF (3 * 64 * SSTR)
#define ATTN_SMEM_BYTES (4 * 64 * SSTR * 4)   // 69632 B

__global__ void __launch_bounds__(256) attn_kernel(
    const float* __restrict__ qkv, float* __restrict__ ctx)
{
    extern __shared__ __align__(16) float sm[];
    float* Qs = sm + QS_OFF;   // [64][68]  Q tile (row-major, d contiguous)
    float* Kt = sm + KT_OFF;   // [64][68]  K tile transposed: Kt[d][j]
    float* Vs = sm + VS_OFF;   // [64][68]  V tile (row s, d contiguous)
    float* Ps = sm + PS_OFF;   // [64][68]  probabilities

    const int t  = threadIdx.x;
    const int c  = t & 15;          // column group (4 cols)
    const int r  = t >> 4;          // row group (4 rows)
    const int qt = (int)(gridDim.x - 1) - (int)blockIdx.x;  // long blocks first
    const int bh = blockIdx.y;
    const int b  = bh >> 4;
    const int h  = bh & 15;
    const int q0 = qt * TQ;

    const size_t rstride = 3 * D_;
    const float* Qg = qkv + (size_t)b * L_ * rstride + (size_t)h * HD_;
    const float* Kg = Qg + D_;
    const float* Vg = Qg + 2 * D_;

    // ---- load Q tile (64 x 64 floats, coalesced float4) ----
    #pragma unroll
    for (int i = 0; i < 4; i++) {
        int idx = t + i * 256;
        int row = idx >> 4;
        int c4  = (idx & 15) * 4;
        float4 v = *(const float4*)(Qg + (size_t)(q0 + row) * rstride + c4);
        *(float4*)(Qs + row * SSTR + c4) = v;
    }

    float m_i[4], l_i[4], acc[4][4];
    #pragma unroll
    for (int ii = 0; ii < 4; ii++) {
        m_i[ii] = -1e30f;
        l_i[ii] = 0.0f;
        #pragma unroll
        for (int jj = 0; jj < 4; jj++) acc[ii][jj] = 0.0f;
    }

    const float scale = 0.125f;  // 1/sqrt(64)

    for (int kt = 0; kt <= qt; kt++) {
        const int k0 = kt * TQ;

        // ---- load K (transposed into Kt[d][j]) and V (natural) ----
        #pragma unroll
        for (int i = 0; i < 4; i++) {
            int idx = t + i * 256;
            int row = idx >> 4;           // seq offset j within tile
            int c4  = (idx & 15) * 4;     // head-dim d
            float4 kv = *(const float4*)(Kg + (size_t)(k0 + row) * rstride + c4);
            Kt[(c4 + 0) * SSTR + row] = kv.x;
            Kt[(c4 + 1) * SSTR + row] = kv.y;
            Kt[(c4 + 2) * SSTR + row] = kv.z;
            Kt[(c4 + 3) * SSTR + row] = kv.w;
            float4 vv = *(const float4*)(Vg + (size_t)(k0 + row) * rstride + c4);
            *(float4*)(Vs + row * SSTR + c4) = vv;
        }
        __syncthreads();

        // ---- S = Q K^T  (4x4 per thread) ----
        float s[4][4];
        #pragma unroll
        for (int ii = 0; ii < 4; ii++)
            #pragma unroll
            for (int jj = 0; jj < 4; jj++) s[ii][jj] = 0.0f;

        #pragma unroll
        for (int d = 0; d < HD_; d += 4) {
            float4 k0v = *(const float4*)(Kt + (d + 0) * SSTR + c * 4);
            float4 k1v = *(const float4*)(Kt + (d + 1) * SSTR + c * 4);
            float4 k2v = *(const float4*)(Kt + (d + 2) * SSTR + c * 4);
            float4 k3v = *(const float4*)(Kt + (d + 3) * SSTR + c * 4);
            #pragma unroll
            for (int ii = 0; ii < 4; ii++) {
                float4 q4 = *(const float4*)(Qs + (r * 4 + ii) * SSTR + d);
                s[ii][0] = fmaf(q4.x, k0v.x, fmaf(q4.y, k1v.x, fmaf(q4.z, k2v.x, fmaf(q4.w, k3v.x, s[ii][0]))));
                s[ii][1] = fmaf(q4.x, k0v.y, fmaf(q4.y, k1v.y, fmaf(q4.z, k2v.y, fmaf(q4.w, k3v.y, s[ii][1]))));
                s[ii][2] = fmaf(q4.x, k0v.z, fmaf(q4.y, k1v.z, fmaf(q4.z, k2v.z, fmaf(q4.w, k3v.z, s[ii][2]))));
                s[ii][3] = fmaf(q4.x, k0v.w, fmaf(q4.y, k1v.w, fmaf(q4.z, k2v.w, fmaf(q4.w, k3v.w, s[ii][3]))));
            }
        }

        // ---- scale + causal mask (only the diagonal tile needs masking) ----
        if (kt == qt) {
            #pragma unroll
            for (int ii = 0; ii < 4; ii++)
                #pragma unroll
                for (int jj = 0; jj < 4; jj++) {
                    float v = s[ii][jj] * scale;
                    s[ii][jj] = ((c * 4 + jj) > (r * 4 + ii)) ? -1e30f : v;
                }
        } else {
            #pragma unroll
            for (int ii = 0; ii < 4; ii++)
                #pragma unroll
                for (int jj = 0; jj < 4; jj++) s[ii][jj] *= scale;
        }

        // ---- online softmax (per-row butterfly over the 16 column lanes) ----
        #pragma unroll
        for (int ii = 0; ii < 4; ii++) {
            float mx = fmaxf(fmaxf(s[ii][0], s[ii][1]), fmaxf(s[ii][2], s[ii][3]));
            mx = fmaxf(mx, __shfl_xor_sync(0xffffffffu, mx, 8));
            mx = fmaxf(mx, __shfl_xor_sync(0xffffffffu, mx, 4));
            mx = fmaxf(mx, __shfl_xor_sync(0xffffffffu, mx, 2));
            mx = fmaxf(mx, __shfl_xor_sync(0xffffffffu, mx, 1));
            float mnew  = fmaxf(m_i[ii], mx);
            float alpha = __expf(m_i[ii] - mnew);
            float rs = 0.0f;
            #pragma unroll
            for (int jj = 0; jj < 4; jj++) {
                s[ii][jj] = __expf(s[ii][jj] - mnew);
                rs += s[ii][jj];
            }
            rs += __shfl_xor_sync(0xffffffffu, rs, 8);
            rs += __shfl_xor_sync(0xffffffffu, rs, 4);
            rs += __shfl_xor_sync(0xffffffffu, rs, 2);
            rs += __shfl_xor_sync(0xffffffffu, rs, 1);
            l_i[ii] = l_i[ii] * alpha + rs;
            m_i[ii] = mnew;
            #pragma unroll
            for (int jj = 0; jj < 4; jj++) acc[ii][jj] *= alpha;
        }

        // ---- write P to smem ----
        #pragma unroll
        for (int ii = 0; ii < 4; ii++) {
            float4 p4 = make_float4(s[ii][0], s[ii][1], s[ii][2], s[ii][3]);
            *(float4*)(Ps + (r * 4 + ii) * SSTR + c * 4) = p4;
        }
        __syncthreads();

        // ---- O += P V  (4x4 per thread) ----
        #pragma unroll
        for (int s4 = 0; s4 < TQ; s4 += 4) {
            float4 v0 = *(const float4*)(Vs + (s4 + 0) * SSTR + c * 4);
            float4 v1 = *(const float4*)(Vs + (s4 + 1) * SSTR + c * 4);
            float4 v2 = *(const float4*)(Vs + (s4 + 2) * SSTR + c * 4);
            float4 v3 = *(const float4*)(Vs + (s4 + 3) * SSTR + c * 4);
            #pragma unroll
            for (int ii = 0; ii < 4; ii++) {
                float4 p4 = *(const float4*)(Ps + (r * 4 + ii) * SSTR + s4);
                acc[ii][0] = fmaf(p4.x, v0.x, fmaf(p4.y, v1.x, fmaf(p4.z, v2.x, fmaf(p4.w, v3.x, acc[ii][0]))));
                acc[ii][1] = fmaf(p4.x, v0.y, fmaf(p4.y, v1.y, fmaf(p4.z, v2.y, fmaf(p4.w, v3.y, acc[ii][1]))));
                acc[ii][2] = fmaf(p4.x, v0.z, fmaf(p4.y, v1.z, fmaf(p4.z, v2.z, fmaf(p4.w, v3.z, acc[ii][2]))));
                acc[ii][3] = fmaf(p4.x, v0.w, fmaf(p4.y, v1.w, fmaf(p4.z, v2.w, fmaf(p4.w, v3.w, acc[ii][3]))));
            }
        }
        __syncthreads();   // protect Kt/Vs/Ps before next iteration's loads
    }

    // ---- finalize + write context [B,L,D] ----
    #pragma unroll
    for (int ii = 0; ii < 4; ii++) {
        float inv = 1.0f / l_i[ii];
        int row = q0 + r * 4 + ii;
        float4 o = make_float4(acc[ii][0] * inv, acc[ii][1] * inv,
                               acc[ii][2] * inv, acc[ii][3] * inv);
        *(float4*)(ctx + ((size_t)b * L_ + row) * D_ + h * HD_ + c * 4) = o;
    }
}

// ---------------------------------------------------------------------------
// kernel_launch — graph-capturable, allocation-free
// ---------------------------------------------------------------------------
extern "C" void kernel_launch(void* const* d_in, const int* in_sizes, int n_in,
                              void* d_out, int out_size)
{
    (void)in_sizes; (void)n_in; (void)out_size;
    const float* x     = (const float*)d_in[0];
    const float* w_qkv = (const float*)d_in[1];
    const float* w_out = (const float*)d_in[2];
    float* out = (float*)d_out;

    float* qkv_ptr = nullptr;
    float* ctx_ptr = nullptr;
    cudaGetSymbolAddress((void**)&qkv_ptr, g_qkv);
    cudaGetSymbolAddress((void**)&ctx_ptr, g_ctx);

    cudaFuncSetAttribute(attn_kernel,
                         cudaFuncAttributeMaxDynamicSharedMemorySize,
                         ATTN_SMEM_BYTES);

    // 1) QKV projection: [4096,3072] = x[4096,1024] @ w_qkv[3072,1024]^T
    {
        dim3 grid(3 * D_ / BN, TOK / BM);
        sgemm_nt<<<grid, 256>>>(x, w_qkv, qkv_ptr, TOK, 3 * D_, D_);
    }

    // 2) Fused causal attention -> ctx [B,L,D]
    {
        dim3 grid(L_ / TQ, B_ * H_);
        attn_kernel<<<grid, 256, ATTN_SMEM_BYTES>>>(qkv_ptr, ctx_ptr);
    }

    // 3) Output projection: out[4096,1024] = ctx @ w_out[1024,1024]^T
    {
        dim3 grid(D_ / BN, TOK / BM);
        sgemm_nt<<<grid, 256>>>(ctx_ptr, w_out, out, TOK, D_, D_);
    }
}

// round 5
// speedup vs baseline: 1.3617x; 1.3617x over previous
#include <cuda_runtime.h>
#include <cuda_bf16.h>
#include <cstdint>
#include <cstddef>

// Problem constants
#define B_   2
#define L_   2048
#define D_   1024
#define H_   16
#define HD_  64
#define TOK  (B_ * L_)          // 4096 tokens

// ---------------------------------------------------------------------------
// Scratch (__device__ globals; no cudaMalloc allowed)
// ---------------------------------------------------------------------------
__device__ __align__(16) float g_qkv[(size_t)TOK * 3 * D_];   // [tok, 3D]
__device__ __align__(16) float g_ctx[(size_t)TOK * D_];       // [tok, D]
__device__ __align__(16) __nv_bfloat16 g_xh[(size_t)TOK * D_];
__device__ __align__(16) __nv_bfloat16 g_xl[(size_t)TOK * D_];
__device__ __align__(16) __nv_bfloat16 g_wqh[(size_t)3 * D_ * D_];
__device__ __align__(16) __nv_bfloat16 g_wql[(size_t)3 * D_ * D_];
__device__ __align__(16) __nv_bfloat16 g_woh[(size_t)D_ * D_];
__device__ __align__(16) __nv_bfloat16 g_wol[(size_t)D_ * D_];
__device__ __align__(16) __nv_bfloat16 g_ch[(size_t)TOK * D_];
__device__ __align__(16) __nv_bfloat16 g_cl[(size_t)TOK * D_];

// ---------------------------------------------------------------------------
// mma.sync m16n8k16 bf16 (sm_80+; works on plain sm_100 target)
// ---------------------------------------------------------------------------
__device__ __forceinline__ void mma16816(float* c, const uint32_t* a, const uint32_t* b) {
    asm volatile("mma.sync.aligned.m16n8k16.row.col.f32.bf16.bf16.f32 "
                 "{%0,%1,%2,%3}, {%4,%5,%6,%7}, {%8,%9}, {%0,%1,%2,%3};"
                 : "+f"(c[0]), "+f"(c[1]), "+f"(c[2]), "+f"(c[3])
                 : "r"(a[0]), "r"(a[1]), "r"(a[2]), "r"(a[3]),
                   "r"(b[0]), "r"(b[1]));
}

// ---------------------------------------------------------------------------
// split fp32 -> bf16 hi + bf16 lo
// ---------------------------------------------------------------------------
__global__ void __launch_bounds__(256) split_bf16(
    const float* __restrict__ in, __nv_bfloat16* __restrict__ hi,
    __nv_bfloat16* __restrict__ lo, int n4)
{
    int i = blockIdx.x * 256 + threadIdx.x;
    if (i >= n4) return;
    float4 v = ((const float4*)in)[i];
    __nv_bfloat16 h0 = __float2bfloat16(v.x);
    __nv_bfloat16 h1 = __float2bfloat16(v.y);
    __nv_bfloat16 h2 = __float2bfloat16(v.z);
    __nv_bfloat16 h3 = __float2bfloat16(v.w);
    __nv_bfloat16 l0 = __float2bfloat16(v.x - __bfloat162float(h0));
    __nv_bfloat16 l1 = __float2bfloat16(v.y - __bfloat162float(h1));
    __nv_bfloat16 l2 = __float2bfloat16(v.z - __bfloat162float(h2));
    __nv_bfloat16 l3 = __float2bfloat16(v.w - __bfloat162float(h3));
    __nv_bfloat162 hv0 = {h0, h1}, hv1 = {h2, h3};
    __nv_bfloat162 lv0 = {l0, l1}, lv1 = {l2, l3};
    ((__nv_bfloat162*)hi)[i * 2 + 0] = hv0;
    ((__nv_bfloat162*)hi)[i * 2 + 1] = hv1;
    ((__nv_bfloat162*)lo)[i * 2 + 0] = lv0;
    ((__nv_bfloat162*)lo)[i * 2 + 1] = lv1;
}

// ---------------------------------------------------------------------------
// Tensor-core GEMM via mma.sync:
//   C[M,N] = (Ah+Al)[M,K] * (Bh+Bl)[N,K]^T   (split-bf16, f32 accumulate,
//   dropping the Al*Bl term: ~2^-18 relative)
// 128x128 CTA tile, BK=32, 512 threads (16 warps, 4x4), 32x32 warp tile.
// Smem row stride 40 bf16 (80B = 20 words): conflict-free for both the
// float4 fills and the m16n8k16 fragment LDS.32 pattern.
// ---------------------------------------------------------------------------
#define SROW 40

__global__ void __launch_bounds__(512) gemm_mma(
    const __nv_bfloat16* __restrict__ Ah, const __nv_bfloat16* __restrict__ Al,
    const __nv_bfloat16* __restrict__ Bh, const __nv_bfloat16* __restrict__ Bl,
    float* __restrict__ C, int N, int K)
{
    __shared__ __align__(16) __nv_bfloat16 sAh[128 * SROW];
    __shared__ __align__(16) __nv_bfloat16 sAl[128 * SROW];
    __shared__ __align__(16) __nv_bfloat16 sBh[128 * SROW];
    __shared__ __align__(16) __nv_bfloat16 sBl[128 * SROW];

    const int tid  = threadIdx.x;
    const int lane = tid & 31;
    const int warp = tid >> 5;
    const int wm   = warp >> 2;         // 0..3
    const int wn   = warp & 3;          // 0..3
    const int bm   = blockIdx.y * 128;
    const int bn   = blockIdx.x * 128;

    // global->smem mapping: thread loads one 16B chunk (8 bf16) per matrix
    const int lrow = tid >> 2;          // 0..127
    const int lc16 = tid & 3;           // 0..3
    const __nv_bfloat16* gAh = Ah + (size_t)(bm + lrow) * K + lc16 * 8;
    const __nv_bfloat16* gAl = Al + (size_t)(bm + lrow) * K + lc16 * 8;
    const __nv_bfloat16* gBh = Bh + (size_t)(bn + lrow) * K + lc16 * 8;
    const __nv_bfloat16* gBl = Bl + (size_t)(bn + lrow) * K + lc16 * 8;
    const int srow = lrow * SROW + lc16 * 8;

    float acc[2][4][4];
    #pragma unroll
    for (int i = 0; i < 2; i++)
        #pragma unroll
        for (int j = 0; j < 4; j++)
            #pragma unroll
            for (int e = 0; e < 4; e++) acc[i][j][e] = 0.0f;

    uint4 pAh = *(const uint4*)gAh;
    uint4 pAl = *(const uint4*)gAl;
    uint4 pBh = *(const uint4*)gBh;
    uint4 pBl = *(const uint4*)gBl;

    const int nk = K / 32;
    for (int kt = 0; kt < nk; kt++) {
        *(uint4*)(sAh + srow) = pAh;
        *(uint4*)(sAl + srow) = pAl;
        *(uint4*)(sBh + srow) = pBh;
        *(uint4*)(sBl + srow) = pBl;
        __syncthreads();

        if (kt + 1 < nk) {
            const int ko = (kt + 1) * 32;
            pAh = *(const uint4*)(gAh + ko);
            pAl = *(const uint4*)(gAl + ko);
            pBh = *(const uint4*)(gBh + ko);
            pBl = *(const uint4*)(gBl + ko);
        }

        #pragma unroll
        for (int ks = 0; ks < 32; ks += 16) {
            const int kf = ks + (lane & 3) * 2;        // fragment k offset
            uint32_t fAh[2][4], fAl[2][4];
            #pragma unroll
            for (int i = 0; i < 2; i++) {
                const int m = wm * 32 + i * 16 + (lane >> 2);
                fAh[i][0] = *(const uint32_t*)(sAh + m * SROW + kf);
                fAh[i][1] = *(const uint32_t*)(sAh + (m + 8) * SROW + kf);
                fAh[i][2] = *(const uint32_t*)(sAh + m * SROW + kf + 8);
                fAh[i][3] = *(const uint32_t*)(sAh + (m + 8) * SROW + kf + 8);
                fAl[i][0] = *(const uint32_t*)(sAl + m * SROW + kf);
                fAl[i][1] = *(const uint32_t*)(sAl + (m + 8) * SROW + kf);
                fAl[i][2] = *(const uint32_t*)(sAl + m * SROW + kf + 8);
                fAl[i][3] = *(const uint32_t*)(sAl + (m + 8) * SROW + kf + 8);
            }
            uint32_t fBh[4][2], fBl[4][2];
            #pragma unroll
            for (int j = 0; j < 4; j++) {
                const int n = wn * 32 + j * 8 + (lane >> 2);
                fBh[j][0] = *(const uint32_t*)(sBh + n * SROW + kf);
                fBh[j][1] = *(const uint32_t*)(sBh + n * SROW + kf + 8);
                fBl[j][0] = *(const uint32_t*)(sBl + n * SROW + kf);
                fBl[j][1] = *(const uint32_t*)(sBl + n * SROW + kf + 8);
            }
            #pragma unroll
            for (int i = 0; i < 2; i++)
                #pragma unroll
                for (int j = 0; j < 4; j++) {
                    mma16816(acc[i][j], fAh[i], fBh[j]);
                    mma16816(acc[i][j], fAh[i], fBl[j]);
                    mma16816(acc[i][j], fAl[i], fBh[j]);
                }
        }
        __syncthreads();
    }

    // epilogue: c0,c1 -> (m, n0..n0+1); c2,c3 -> (m+8, n0..n0+1)
    #pragma unroll
    for (int i = 0; i < 2; i++) {
        const int m = bm + wm * 32 + i * 16 + (lane >> 2);
        #pragma unroll
        for (int j = 0; j < 4; j++) {
            const int n = bn + wn * 32 + j * 8 + (lane & 3) * 2;
            *(float2*)(C + (size_t)m * N + n)       = make_float2(acc[i][j][0], acc[i][j][1]);
            *(float2*)(C + (size_t)(m + 8) * N + n) = make_float2(acc[i][j][2], acc[i][j][3]);
        }
    }
}

// ---------------------------------------------------------------------------
// Fused causal flash-attention (Round 1, unchanged — proven correct)
// ---------------------------------------------------------------------------
#define TQ 64
#define SSTR 68
#define QS_OFF 0
#define KT_OFF (64 * SSTR)
#define VS_OFF (2 * 64 * SSTR)
#define PS_OFF (3 * 64 * SSTR)
#define ATTN_SMEM_BYTES (4 * 64 * SSTR * 4)

__global__ void __launch_bounds__(256) attn_kernel(
    const float* __restrict__ qkv, float* __restrict__ ctx)
{
    extern __shared__ __align__(16) float sm[];
    float* Qs = sm + QS_OFF;
    float* Kt = sm + KT_OFF;
    float* Vs = sm + VS_OFF;
    float* Ps = sm + PS_OFF;

    const int t  = threadIdx.x;
    const int c  = t & 15;
    const int r  = t >> 4;
    const int qt = (int)(gridDim.x - 1) - (int)blockIdx.x;
    const int bh = blockIdx.y;
    const int b  = bh >> 4;
    const int h  = bh & 15;
    const int q0 = qt * TQ;

    const size_t rstride = 3 * D_;
    const float* Qg = qkv + (size_t)b * L_ * rstride + (size_t)h * HD_;
    const float* Kg = Qg + D_;
    const float* Vg = Qg + 2 * D_;

    #pragma unroll
    for (int i = 0; i < 4; i++) {
        int idx = t + i * 256;
        int row = idx >> 4;
        int c4  = (idx & 15) * 4;
        float4 v = *(const float4*)(Qg + (size_t)(q0 + row) * rstride + c4);
        *(float4*)(Qs + row * SSTR + c4) = v;
    }

    float m_i[4], l_i[4], acc[4][4];
    #pragma unroll
    for (int ii = 0; ii < 4; ii++) {
        m_i[ii] = -1e30f; l_i[ii] = 0.0f;
        #pragma unroll
        for (int jj = 0; jj < 4; jj++) acc[ii][jj] = 0.0f;
    }

    const float scale = 0.125f;

    for (int kt = 0; kt <= qt; kt++) {
        const int k0 = kt * TQ;
        #pragma unroll
        for (int i = 0; i < 4; i++) {
            int idx = t + i * 256;
            int row = idx >> 4;
            int c4  = (idx & 15) * 4;
            float4 kv = *(const float4*)(Kg + (size_t)(k0 + row) * rstride + c4);
            Kt[(c4 + 0) * SSTR + row] = kv.x;
            Kt[(c4 + 1) * SSTR + row] = kv.y;
            Kt[(c4 + 2) * SSTR + row] = kv.z;
            Kt[(c4 + 3) * SSTR + row] = kv.w;
            float4 vv = *(const float4*)(Vg + (size_t)(k0 + row) * rstride + c4);
            *(float4*)(Vs + row * SSTR + c4) = vv;
        }
        __syncthreads();

        float s[4][4];
        #pragma unroll
        for (int ii = 0; ii < 4; ii++)
            #pragma unroll
            for (int jj = 0; jj < 4; jj++) s[ii][jj] = 0.0f;

        #pragma unroll
        for (int d = 0; d < HD_; d += 4) {
            float4 k0v = *(const float4*)(Kt + (d + 0) * SSTR + c * 4);
            float4 k1v = *(const float4*)(Kt + (d + 1) * SSTR + c * 4);
            float4 k2v = *(const float4*)(Kt + (d + 2) * SSTR + c * 4);
            float4 k3v = *(const float4*)(Kt + (d + 3) * SSTR + c * 4);
            #pragma unroll
            for (int ii = 0; ii < 4; ii++) {
                float4 q4 = *(const float4*)(Qs + (r * 4 + ii) * SSTR + d);
                s[ii][0] = fmaf(q4.x, k0v.x, fmaf(q4.y, k1v.x, fmaf(q4.z, k2v.x, fmaf(q4.w, k3v.x, s[ii][0]))));
                s[ii][1] = fmaf(q4.x, k0v.y, fmaf(q4.y, k1v.y, fmaf(q4.z, k2v.y, fmaf(q4.w, k3v.y, s[ii][1]))));
                s[ii][2] = fmaf(q4.x, k0v.z, fmaf(q4.y, k1v.z, fmaf(q4.z, k2v.z, fmaf(q4.w, k3v.z, s[ii][2]))));
                s[ii][3] = fmaf(q4.x, k0v.w, fmaf(q4.y, k1v.w, fmaf(q4.z, k2v.w, fmaf(q4.w, k3v.w, s[ii][3]))));
            }
        }

        if (kt == qt) {
            #pragma unroll
            for (int ii = 0; ii < 4; ii++)
                #pragma unroll
                for (int jj = 0; jj < 4; jj++) {
                    float v = s[ii][jj] * scale;
                    s[ii][jj] = ((c * 4 + jj) > (r * 4 + ii)) ? -1e30f : v;
                }
        } else {
            #pragma unroll
            for (int ii = 0; ii < 4; ii++)
                #pragma unroll
                for (int jj = 0; jj < 4; jj++) s[ii][jj] *= scale;
        }

        #pragma unroll
        for (int ii = 0; ii < 4; ii++) {
            float mx = fmaxf(fmaxf(s[ii][0], s[ii][1]), fmaxf(s[ii][2], s[ii][3]));
            mx = fmaxf(mx, __shfl_xor_sync(0xffffffffu, mx, 8));
            mx = fmaxf(mx, __shfl_xor_sync(0xffffffffu, mx, 4));
            mx = fmaxf(mx, __shfl_xor_sync(0xffffffffu, mx, 2));
            mx = fmaxf(mx, __shfl_xor_sync(0xffffffffu, mx, 1));
            float mnew  = fmaxf(m_i[ii], mx);
            float alpha = __expf(m_i[ii] - mnew);
            float rs = 0.0f;
            #pragma unroll
            for (int jj = 0; jj < 4; jj++) {
                s[ii][jj] = __expf(s[ii][jj] - mnew);
                rs += s[ii][jj];
            }
            rs += __shfl_xor_sync(0xffffffffu, rs, 8);
            rs += __shfl_xor_sync(0xffffffffu, rs, 4);
            rs += __shfl_xor_sync(0xffffffffu, rs, 2);
            rs += __shfl_xor_sync(0xffffffffu, rs, 1);
            l_i[ii] = l_i[ii] * alpha + rs;
            m_i[ii] = mnew;
            #pragma unroll
            for (int jj = 0; jj < 4; jj++) acc[ii][jj] *= alpha;
        }

        #pragma unroll
        for (int ii = 0; ii < 4; ii++) {
            *(float4*)(Ps + (r * 4 + ii) * SSTR + c * 4) =
                make_float4(s[ii][0], s[ii][1], s[ii][2], s[ii][3]);
        }
        __syncthreads();

        #pragma unroll
        for (int s4 = 0; s4 < TQ; s4 += 4) {
            float4 v0 = *(const float4*)(Vs + (s4 + 0) * SSTR + c * 4);
            float4 v1 = *(const float4*)(Vs + (s4 + 1) * SSTR + c * 4);
            float4 v2 = *(const float4*)(Vs + (s4 + 2) * SSTR + c * 4);
            float4 v3 = *(const float4*)(Vs + (s4 + 3) * SSTR + c * 4);
            #pragma unroll
            for (int ii = 0; ii < 4; ii++) {
                float4 p4 = *(const float4*)(Ps + (r * 4 + ii) * SSTR + s4);
                acc[ii][0] = fmaf(p4.x, v0.x, fmaf(p4.y, v1.x, fmaf(p4.z, v2.x, fmaf(p4.w, v3.x, acc[ii][0]))));
                acc[ii][1] = fmaf(p4.x, v0.y, fmaf(p4.y, v1.y, fmaf(p4.z, v2.y, fmaf(p4.w, v3.y, acc[ii][1]))));
                acc[ii][2] = fmaf(p4.x, v0.z, fmaf(p4.y, v1.z, fmaf(p4.z, v2.z, fmaf(p4.w, v3.z, acc[ii][2]))));
                acc[ii][3] = fmaf(p4.x, v0.w, fmaf(p4.y, v1.w, fmaf(p4.z, v2.w, fmaf(p4.w, v3.w, acc[ii][3]))));
            }
        }
        __syncthreads();
    }

    #pragma unroll
    for (int ii = 0; ii < 4; ii++) {
        float inv = 1.0f / l_i[ii];
        int row = q0 + r * 4 + ii;
        *(float4*)(ctx + ((size_t)b * L_ + row) * D_ + h * HD_ + c * 4) =
            make_float4(acc[ii][0] * inv, acc[ii][1] * inv, acc[ii][2] * inv, acc[ii][3] * inv);
    }
}

// ---------------------------------------------------------------------------
// kernel_launch — graph-capturable, allocation-free
// ---------------------------------------------------------------------------
extern "C" void kernel_launch(void* const* d_in, const int* in_sizes, int n_in,
                              void* d_out, int out_size)
{
    (void)in_sizes; (void)n_in; (void)out_size;
    const float* x     = (const float*)d_in[0];
    const float* w_qkv = (const float*)d_in[1];
    const float* w_out = (const float*)d_in[2];
    float* out = (float*)d_out;

    float *qkv_ptr, *ctx_ptr;
    __nv_bfloat16 *xh, *xl, *wqh, *wql, *woh, *wol, *ch, *cl;
    cudaGetSymbolAddress((void**)&qkv_ptr, g_qkv);
    cudaGetSymbolAddress((void**)&ctx_ptr, g_ctx);
    cudaGetSymbolAddress((void**)&xh, g_xh);
    cudaGetSymbolAddress((void**)&xl, g_xl);
    cudaGetSymbolAddress((void**)&wqh, g_wqh);
    cudaGetSymbolAddress((void**)&wql, g_wql);
    cudaGetSymbolAddress((void**)&woh, g_woh);
    cudaGetSymbolAddress((void**)&wol, g_wol);
    cudaGetSymbolAddress((void**)&ch, g_ch);
    cudaGetSymbolAddress((void**)&cl, g_cl);

    cudaFuncSetAttribute(attn_kernel,
                         cudaFuncAttributeMaxDynamicSharedMemorySize, ATTN_SMEM_BYTES);

    // split inputs to bf16 hi/lo
    split_bf16<<<(TOK * D_) / 1024, 256>>>(x, xh, xl, (TOK * D_) / 4);
    split_bf16<<<(3 * D_ * D_) / 1024, 256>>>(w_qkv, wqh, wql, (3 * D_ * D_) / 4);
    split_bf16<<<(D_ * D_) / 1024, 256>>>(w_out, woh, wol, (D_ * D_) / 4);

    // 1) QKV projection on tensor cores (mma.sync)
    {
        dim3 grid(3 * D_ / 128, TOK / 128);
        gemm_mma<<<grid, 512>>>(xh, xl, wqh, wql, qkv_ptr, 3 * D_, D_);
    }
    // 2) fused causal attention
    {
        dim3 grid(L_ / TQ, B_ * H_);
        attn_kernel<<<grid, 256, ATTN_SMEM_BYTES>>>(qkv_ptr, ctx_ptr);
    }
    // 3) split ctx, output projection on tensor cores
    split_bf16<<<(TOK * D_) / 1024, 256>>>(ctx_ptr, ch, cl, (TOK * D_) / 4);
    {
        dim3 grid(D_ / 128, TOK / 128);
        gemm_mma<<<grid, 512>>>(ch, cl, woh, wol, out, D_, D_);
    }
}

// round 6
// speedup vs baseline: 1.8901x; 1.3880x over previous
#include <cuda_runtime.h>
#include <cuda_bf16.h>
#include <cstdint>
#include <cstddef>

// Problem constants
#define B_   2
#define L_   2048
#define D_   1024
#define H_   16
#define HD_  64
#define TOK  (B_ * L_)          // 4096 tokens

// ---------------------------------------------------------------------------
// Scratch (__device__ globals; no cudaMalloc allowed)
// ---------------------------------------------------------------------------
__device__ __align__(16) __nv_bfloat16 g_xh[(size_t)TOK * D_];
__device__ __align__(16) __nv_bfloat16 g_xl[(size_t)TOK * D_];
__device__ __align__(16) __nv_bfloat16 g_wqh[(size_t)3 * D_ * D_];
__device__ __align__(16) __nv_bfloat16 g_wql[(size_t)3 * D_ * D_];
__device__ __align__(16) __nv_bfloat16 g_woh[(size_t)D_ * D_];
__device__ __align__(16) __nv_bfloat16 g_wol[(size_t)D_ * D_];
// head-major split qkv: [part(q/k/v)][b][h][l][64]
__device__ __align__(16) __nv_bfloat16 g_qkvh[(size_t)3 * TOK * D_];
__device__ __align__(16) __nv_bfloat16 g_qkvl[(size_t)3 * TOK * D_];
// attention context, split: [tok][1024]
__device__ __align__(16) __nv_bfloat16 g_ch[(size_t)TOK * D_];
__device__ __align__(16) __nv_bfloat16 g_cl[(size_t)TOK * D_];

// ---------------------------------------------------------------------------
// Helpers
// ---------------------------------------------------------------------------
__device__ __forceinline__ uint32_t smem_u32(const void* p) {
    uint32_t a;
    asm("{ .reg .u64 t; cvta.to.shared.u64 t, %1; cvt.u32.u64 %0, t; }" : "=r"(a) : "l"(p));
    return a;
}

__device__ __forceinline__ void mma16816(float* c, const uint32_t* a, const uint32_t* b) {
    asm volatile("mma.sync.aligned.m16n8k16.row.col.f32.bf16.bf16.f32 "
                 "{%0,%1,%2,%3}, {%4,%5,%6,%7}, {%8,%9}, {%0,%1,%2,%3};"
                 : "+f"(c[0]), "+f"(c[1]), "+f"(c[2]), "+f"(c[3])
                 : "r"(a[0]), "r"(a[1]), "r"(a[2]), "r"(a[3]),
                   "r"(b[0]), "r"(b[1]));
}

__device__ __forceinline__ uint32_t pack_bf(__nv_bfloat16 lo, __nv_bfloat16 hi) {
    return (uint32_t)__bfloat16_as_ushort(lo) | ((uint32_t)__bfloat16_as_ushort(hi) << 16);
}
__device__ __forceinline__ uint32_t pack_us(uint16_t lo, uint16_t hi) {
    return (uint32_t)lo | ((uint32_t)hi << 16);
}
// split two floats into packed bf16 hi-pair and lo-pair (element0 in low half)
__device__ __forceinline__ void split_pack2(float x, float y, uint32_t& hp, uint32_t& lp) {
    __nv_bfloat16 hx = __float2bfloat16(x), hy = __float2bfloat16(y);
    __nv_bfloat16 lx = __float2bfloat16(x - __bfloat162float(hx));
    __nv_bfloat16 ly = __float2bfloat16(y - __bfloat162float(hy));
    hp = pack_bf(hx, hy);
    lp = pack_bf(lx, ly);
}

#define CP_ASYNC16(dst, src) \
    asm volatile("cp.async.cg.shared.global [%0], [%1], 16;" :: "r"(dst), "l"(src) : "memory")
#define CP_COMMIT() asm volatile("cp.async.commit_group;" ::: "memory")
#define CP_WAIT1()  asm volatile("cp.async.wait_group 1;" ::: "memory")
#define CP_WAIT0()  asm volatile("cp.async.wait_group 0;" ::: "memory")

// ---------------------------------------------------------------------------
// split fp32 -> bf16 hi + lo (for x, w_qkv, w_out)
// ---------------------------------------------------------------------------
__global__ void __launch_bounds__(256) split_bf16(
    const float* __restrict__ in, __nv_bfloat16* __restrict__ hi,
    __nv_bfloat16* __restrict__ lo, int n4)
{
    int i = blockIdx.x * 256 + threadIdx.x;
    if (i >= n4) return;
    float4 v = ((const float4*)in)[i];
    __nv_bfloat16 h0 = __float2bfloat16(v.x);
    __nv_bfloat16 h1 = __float2bfloat16(v.y);
    __nv_bfloat16 h2 = __float2bfloat16(v.z);
    __nv_bfloat16 h3 = __float2bfloat16(v.w);
    __nv_bfloat16 l0 = __float2bfloat16(v.x - __bfloat162float(h0));
    __nv_bfloat16 l1 = __float2bfloat16(v.y - __bfloat162float(h1));
    __nv_bfloat16 l2 = __float2bfloat16(v.z - __bfloat162float(h2));
    __nv_bfloat16 l3 = __float2bfloat16(v.w - __bfloat162float(h3));
    ((uint32_t*)hi)[i * 2 + 0] = pack_bf(h0, h1);
    ((uint32_t*)hi)[i * 2 + 1] = pack_bf(h2, h3);
    ((uint32_t*)lo)[i * 2 + 0] = pack_bf(l0, l1);
    ((uint32_t*)lo)[i * 2 + 1] = pack_bf(l2, l3);
}

// ---------------------------------------------------------------------------
// GEMM core (shared by both gemm kernels): 128x128 tile, BK=32, 512 thr.
// ---------------------------------------------------------------------------
#define SROW 40

#define GEMM_BODY(Ah, Al, Bh, Bl, K)                                           \
    __shared__ __align__(16) __nv_bfloat16 sAh[128 * SROW];                    \
    __shared__ __align__(16) __nv_bfloat16 sAl[128 * SROW];                    \
    __shared__ __align__(16) __nv_bfloat16 sBh[128 * SROW];                    \
    __shared__ __align__(16) __nv_bfloat16 sBl[128 * SROW];                    \
    const int tid  = threadIdx.x;                                              \
    const int lane = tid & 31;                                                 \
    const int warp = tid >> 5;                                                 \
    const int wm   = warp >> 2;                                                \
    const int wn   = warp & 3;                                                 \
    const int bm   = blockIdx.y * 128;                                         \
    const int bn   = blockIdx.x * 128;                                         \
    const int lrow = tid >> 2;                                                 \
    const int lc16 = tid & 3;                                                  \
    const __nv_bfloat16* gAh = Ah + (size_t)(bm + lrow) * K + lc16 * 8;        \
    const __nv_bfloat16* gAl = Al + (size_t)(bm + lrow) * K + lc16 * 8;        \
    const __nv_bfloat16* gBh = Bh + (size_t)(bn + lrow) * K + lc16 * 8;        \
    const __nv_bfloat16* gBl = Bl + (size_t)(bn + lrow) * K + lc16 * 8;        \
    const int srow = lrow * SROW + lc16 * 8;                                   \
    float acc[2][4][4];                                                        \
    _Pragma("unroll")                                                          \
    for (int i = 0; i < 2; i++)                                                \
        _Pragma("unroll")                                                      \
        for (int j = 0; j < 4; j++)                                            \
            _Pragma("unroll")                                                  \
            for (int e = 0; e < 4; e++) acc[i][j][e] = 0.0f;                   \
    uint4 pAh = *(const uint4*)gAh;                                            \
    uint4 pAl = *(const uint4*)gAl;                                            \
    uint4 pBh = *(const uint4*)gBh;                                            \
    uint4 pBl = *(const uint4*)gBl;                                            \
    const int nk = K / 32;                                                     \
    for (int kt = 0; kt < nk; kt++) {                                          \
        *(uint4*)(sAh + srow) = pAh;                                           \
        *(uint4*)(sAl + srow) = pAl;                                           \
        *(uint4*)(sBh + srow) = pBh;                                           \
        *(uint4*)(sBl + srow) = pBl;                                           \
        __syncthreads();                                                       \
        if (kt + 1 < nk) {                                                     \
            const int ko = (kt + 1) * 32;                                      \
            pAh = *(const uint4*)(gAh + ko);                                   \
            pAl = *(const uint4*)(gAl + ko);                                   \
            pBh = *(const uint4*)(gBh + ko);                                   \
            pBl = *(const uint4*)(gBl + ko);                                   \
        }                                                                      \
        _Pragma("unroll")                                                      \
        for (int ks = 0; ks < 32; ks += 16) {                                  \
            const int kf = ks + (lane & 3) * 2;                                \
            uint32_t fAh[2][4], fAl[2][4];                                     \
            _Pragma("unroll")                                                  \
            for (int i = 0; i < 2; i++) {                                      \
                const int m = wm * 32 + i * 16 + (lane >> 2);                  \
                fAh[i][0] = *(const uint32_t*)(sAh + m * SROW + kf);           \
                fAh[i][1] = *(const uint32_t*)(sAh + (m + 8) * SROW + kf);     \
                fAh[i][2] = *(const uint32_t*)(sAh + m * SROW + kf + 8);       \
                fAh[i][3] = *(const uint32_t*)(sAh + (m + 8) * SROW + kf + 8); \
                fAl[i][0] = *(const uint32_t*)(sAl + m * SROW + kf);           \
                fAl[i][1] = *(const uint32_t*)(sAl + (m + 8) * SROW + kf);     \
                fAl[i][2] = *(const uint32_t*)(sAl + m * SROW + kf + 8);       \
                fAl[i][3] = *(const uint32_t*)(sAl + (m + 8) * SROW + kf + 8); \
            }                                                                  \
            uint32_t fBh[4][2], fBl[4][2];                                     \
            _Pragma("unroll")                                                  \
            for (int j = 0; j < 4; j++) {                                      \
                const int n = wn * 32 + j * 8 + (lane >> 2);                   \
                fBh[j][0] = *(const uint32_t*)(sBh + n * SROW + kf);           \
                fBh[j][1] = *(const uint32_t*)(sBh + n * SROW + kf + 8);       \
                fBl[j][0] = *(const uint32_t*)(sBl + n * SROW + kf);           \
                fBl[j][1] = *(const uint32_t*)(sBl + n * SROW + kf + 8);       \
            }                                                                  \
            _Pragma("unroll")                                                  \
            for (int i = 0; i < 2; i++)                                        \
                _Pragma("unroll")                                              \
                for (int j = 0; j < 4; j++) {                                  \
                    mma16816(acc[i][j], fAh[i], fBh[j]);                       \
                    mma16816(acc[i][j], fAh[i], fBl[j]);                       \
                    mma16816(acc[i][j], fAl[i], fBh[j]);                       \
                }                                                              \
        }                                                                      \
        __syncthreads();                                                       \
    }

// Out-proj GEMM: fp32 output, row-major C[M,N]
__global__ void __launch_bounds__(512) gemm_mma(
    const __nv_bfloat16* __restrict__ Ah, const __nv_bfloat16* __restrict__ Al,
    const __nv_bfloat16* __restrict__ Bh, const __nv_bfloat16* __restrict__ Bl,
    float* __restrict__ C, int N, int K)
{
    GEMM_BODY(Ah, Al, Bh, Bl, K)
    #pragma unroll
    for (int i = 0; i < 2; i++) {
        const int m = bm + wm * 32 + i * 16 + (lane >> 2);
        #pragma unroll
        for (int j = 0; j < 4; j++) {
            const int n = bn + wn * 32 + j * 8 + (lane & 3) * 2;
            *(float2*)(C + (size_t)m * N + n)       = make_float2(acc[i][j][0], acc[i][j][1]);
            *(float2*)(C + (size_t)(m + 8) * N + n) = make_float2(acc[i][j][2], acc[i][j][3]);
        }
    }
}

// QKV GEMM: writes split bf16 head-major qkv [part][b][h][l][64]
__global__ void __launch_bounds__(512) gemm_mma_qkv(
    const __nv_bfloat16* __restrict__ Ah, const __nv_bfloat16* __restrict__ Al,
    const __nv_bfloat16* __restrict__ Bh, const __nv_bfloat16* __restrict__ Bl,
    __nv_bfloat16* __restrict__ Qh, __nv_bfloat16* __restrict__ Ql, int K)
{
    GEMM_BODY(Ah, Al, Bh, Bl, K)
    #pragma unroll
    for (int i = 0; i < 2; i++) {
        const int m = bm + wm * 32 + i * 16 + (lane >> 2);   // token
        const int bb = m >> 11, ll = m & 2047;
        #pragma unroll
        for (int j = 0; j < 4; j++) {
            const int n = bn + wn * 32 + j * 8 + (lane & 3) * 2;
            const int part = n >> 10, rem = n & 1023, hh = rem >> 6, dd = rem & 63;
            const size_t off = (((size_t)(part * B_ + bb) * H_ + hh) * L_ + ll) * HD_ + dd;
            uint32_t hp, lp;
            split_pack2(acc[i][j][0], acc[i][j][1], hp, lp);
            *(uint32_t*)(Qh + off) = hp;
            *(uint32_t*)(Ql + off) = lp;
            split_pack2(acc[i][j][2], acc[i][j][3], hp, lp);
            *(uint32_t*)(Qh + off + (size_t)8 * HD_) = hp;
            *(uint32_t*)(Ql + off + (size_t)8 * HD_) = lp;
        }
    }
}

// ---------------------------------------------------------------------------
// Tensor-core causal flash attention.
// Block = (b,h) x 128-row Q tile. 256 threads, 8 warps; warp owns 16 rows.
// K/V tiles (64 keys) double-buffered in smem via cp.async.
// Split-bf16 3-mma for both QK^T and P*V.
// ---------------------------------------------------------------------------
#define KSTR  72                         // smem row stride (bf16 elems)
#define AT_TILE  (64 * KSTR * 2)         // 9216 B per matrix tile
#define AT_STAGE (4 * AT_TILE)           // Kh,Kl,Vh,Vl
#define AT_SMEM  (2 * AT_STAGE)          // 73728 B

__global__ void __launch_bounds__(256) attn_mma(
    const __nv_bfloat16* __restrict__ qkvh,
    const __nv_bfloat16* __restrict__ qkvl,
    __nv_bfloat16* __restrict__ ch, __nv_bfloat16* __restrict__ cl)
{
    extern __shared__ __align__(16) char smem[];
    const uint32_t sb = smem_u32(smem);
    const int tid = threadIdx.x, lane = tid & 31, warp = tid >> 5;
    const int qt = (int)gridDim.x - 1 - (int)blockIdx.x;   // long blocks first
    const int bh = blockIdx.y, b = bh >> 4, h = bh & 15;
    const int q0 = qt * 128;
    const size_t PART = (size_t)TOK * D_;
    const size_t headoff = (size_t)bh * L_ * HD_;
    const __nv_bfloat16* Qh = qkvh + headoff;
    const __nv_bfloat16* Ql = qkvl + headoff;
    const __nv_bfloat16* Kh = qkvh + PART + headoff;
    const __nv_bfloat16* Kl = qkvl + PART + headoff;
    const __nv_bfloat16* Vh = qkvh + 2 * PART + headoff;
    const __nv_bfloat16* Vl = qkvl + 2 * PART + headoff;

    const int r0 = q0 + warp * 16 + (lane >> 2);   // this lane's first row

    // Q fragments (hi/lo), loaded once: a-frag layout m16k16, 4 k-steps
    uint32_t qfh[4][4], qfl[4][4];
    {
        const __nv_bfloat16* p0  = Qh + (size_t)r0 * HD_;
        const __nv_bfloat16* p8  = p0 + 8 * HD_;
        const __nv_bfloat16* p0l = Ql + (size_t)r0 * HD_;
        const __nv_bfloat16* p8l = p0l + 8 * HD_;
        #pragma unroll
        for (int t = 0; t < 4; t++) {
            const int d0 = t * 16 + 2 * (lane & 3);
            qfh[t][0] = *(const uint32_t*)(p0 + d0);
            qfh[t][1] = *(const uint32_t*)(p8 + d0);
            qfh[t][2] = *(const uint32_t*)(p0 + d0 + 8);
            qfh[t][3] = *(const uint32_t*)(p8 + d0 + 8);
            qfl[t][0] = *(const uint32_t*)(p0l + d0);
            qfl[t][1] = *(const uint32_t*)(p8l + d0);
            qfl[t][2] = *(const uint32_t*)(p0l + d0 + 8);
            qfl[t][3] = *(const uint32_t*)(p8l + d0 + 8);
        }
    }

    float Oa[8][4];
    #pragma unroll
    for (int j = 0; j < 8; j++)
        #pragma unroll
        for (int e = 0; e < 4; e++) Oa[j][e] = 0.0f;
    float m0 = -1e30f, m1 = -1e30f, l0 = 0.0f, l1 = 0.0f;

    const int ntiles = 2 * qt + 2;

    // -- cp.async tile loader: Kh,Kl,Vh,Vl (64 x 64 bf16 each, stride KSTR) --
    auto load_tile = [&](int kt, int stage) {
        const uint32_t dstbase = sb + stage * AT_STAGE;
        #pragma unroll
        for (int i = 0; i < 2; i++) {
            const int rem = tid + i * 256;          // 0..511
            const int row = rem >> 3, dch = rem & 7;
            const size_t g = (size_t)(kt * 64 + row) * HD_ + dch * 8;
            const uint32_t dof = dstbase + row * (KSTR * 2) + dch * 16;
            CP_ASYNC16(dof + 0 * AT_TILE, Kh + g);
            CP_ASYNC16(dof + 1 * AT_TILE, Kl + g);
            CP_ASYNC16(dof + 2 * AT_TILE, Vh + g);
            CP_ASYNC16(dof + 3 * AT_TILE, Vl + g);
        }
        CP_COMMIT();
    };

    load_tile(0, 0);

    for (int kt = 0; kt < ntiles; kt++) {
        const int stage = kt & 1;
        if (kt + 1 < ntiles) { load_tile(kt + 1, (kt + 1) & 1); CP_WAIT1(); }
        else                 { CP_WAIT0(); }
        __syncthreads();

        const int k0 = kt * 64;
        if (k0 <= q0 + warp * 16 + 15) {          // warp-uniform: any work?
            const char* kph = smem + stage * AT_STAGE;
            const char* kpl = kph + AT_TILE;
            const char* vph = kph + 2 * AT_TILE;
            const char* vpl = kph + 3 * AT_TILE;

            // ---- S = Q K^T ----
            float Sa[8][4];
            #pragma unroll
            for (int j = 0; j < 8; j++)
                #pragma unroll
                for (int e = 0; e < 4; e++) Sa[j][e] = 0.0f;

            #pragma unroll
            for (int j = 0; j < 8; j++) {
                const int key = j * 8 + (lane >> 2);
                const int rowoff = key * (KSTR * 2);
                #pragma unroll
                for (int t = 0; t < 4; t++) {
                    const int off = rowoff + (t * 16 + 2 * (lane & 3)) * 2;
                    uint32_t bhf[2], blf[2];
                    bhf[0] = *(const uint32_t*)(kph + off);
                    bhf[1] = *(const uint32_t*)(kph + off + 16);
                    blf[0] = *(const uint32_t*)(kpl + off);
                    blf[1] = *(const uint32_t*)(kpl + off + 16);
                    mma16816(Sa[j], qfh[t], bhf);
                    mma16816(Sa[j], qfh[t], blf);
                    mma16816(Sa[j], qfl[t], bhf);
                }
            }

            // ---- scale + causal mask ----
            const bool needmask = (k0 + 63 > q0 + warp * 16);
            #pragma unroll
            for (int j = 0; j < 8; j++) {
                #pragma unroll
                for (int e = 0; e < 4; e++) Sa[j][e] *= 0.125f;
                if (needmask) {
                    const int key0 = k0 + j * 8 + 2 * (lane & 3);
                    if (key0     > r0)     Sa[j][0] = -1e30f;
                    if (key0 + 1 > r0)     Sa[j][1] = -1e30f;
                    if (key0     > r0 + 8) Sa[j][2] = -1e30f;
                    if (key0 + 1 > r0 + 8) Sa[j][3] = -1e30f;
                }
            }

            // ---- online softmax (2 rows per lane, quad reductions) ----
            float mx0 = -1e30f, mx1 = -1e30f;
            #pragma unroll
            for (int j = 0; j < 8; j++) {
                mx0 = fmaxf(mx0, fmaxf(Sa[j][0], Sa[j][1]));
                mx1 = fmaxf(mx1, fmaxf(Sa[j][2], Sa[j][3]));
            }
            mx0 = fmaxf(mx0, __shfl_xor_sync(0xffffffffu, mx0, 1));
            mx0 = fmaxf(mx0, __shfl_xor_sync(0xffffffffu, mx0, 2));
            mx1 = fmaxf(mx1, __shfl_xor_sync(0xffffffffu, mx1, 1));
            mx1 = fmaxf(mx1, __shfl_xor_sync(0xffffffffu, mx1, 2));
            const float mn0 = fmaxf(m0, mx0), mn1 = fmaxf(m1, mx1);
            const float a0 = __expf(m0 - mn0), a1 = __expf(m1 - mn1);
            m0 = mn0; m1 = mn1;
            float rs0 = 0.0f, rs1 = 0.0f;
            #pragma unroll
            for (int j = 0; j < 8; j++) {
                Sa[j][0] = __expf(Sa[j][0] - mn0); rs0 += Sa[j][0];
                Sa[j][1] = __expf(Sa[j][1] - mn0); rs0 += Sa[j][1];
                Sa[j][2] = __expf(Sa[j][2] - mn1); rs1 += Sa[j][2];
                Sa[j][3] = __expf(Sa[j][3] - mn1); rs1 += Sa[j][3];
            }
            rs0 += __shfl_xor_sync(0xffffffffu, rs0, 1);
            rs0 += __shfl_xor_sync(0xffffffffu, rs0, 2);
            rs1 += __shfl_xor_sync(0xffffffffu, rs1, 1);
            rs1 += __shfl_xor_sync(0xffffffffu, rs1, 2);
            l0 = l0 * a0 + rs0;
            l1 = l1 * a1 + rs1;
            #pragma unroll
            for (int j = 0; j < 8; j++) {
                Oa[j][0] *= a0; Oa[j][1] *= a0;
                Oa[j][2] *= a1; Oa[j][3] *= a1;
            }

            // ---- O += P V  (P from accumulators, split bf16) ----
            #pragma unroll
            for (int t = 0; t < 4; t++) {
                uint32_t ah[4], al[4];
                split_pack2(Sa[2 * t][0],     Sa[2 * t][1],     ah[0], al[0]);
                split_pack2(Sa[2 * t][2],     Sa[2 * t][3],     ah[1], al[1]);
                split_pack2(Sa[2 * t + 1][0], Sa[2 * t + 1][1], ah[2], al[2]);
                split_pack2(Sa[2 * t + 1][2], Sa[2 * t + 1][3], ah[3], al[3]);
                const int kk = t * 16 + 2 * (lane & 3);
                #pragma unroll
                for (int j = 0; j < 8; j++) {
                    const int n = j * 8 + (lane >> 2);
                    const char* pv  = vph + ((size_t)kk * KSTR + n) * 2;
                    const char* pvl = vpl + ((size_t)kk * KSTR + n) * 2;
                    uint32_t vhf[2], vlf[2];
                    vhf[0] = pack_us(*(const uint16_t*)(pv),
                                     *(const uint16_t*)(pv + KSTR * 2));
                    vhf[1] = pack_us(*(const uint16_t*)(pv + 8 * KSTR * 2),
                                     *(const uint16_t*)(pv + 9 * KSTR * 2));
                    vlf[0] = pack_us(*(const uint16_t*)(pvl),
                                     *(const uint16_t*)(pvl + KSTR * 2));
                    vlf[1] = pack_us(*(const uint16_t*)(pvl + 8 * KSTR * 2),
                                     *(const uint16_t*)(pvl + 9 * KSTR * 2));
                    mma16816(Oa[j], ah, vhf);
                    mma16816(Oa[j], ah, vlf);
                    mma16816(Oa[j], al, vhf);
                }
            }
        }
        __syncthreads();
    }

    // ---- finalize: write ctx hi/lo bf16 [tok][1024] ----
    const float inv0 = 1.0f / l0, inv1 = 1.0f / l1;
    const size_t row_off = (size_t)(b * L_ + r0) * D_ + h * 64;
    #pragma unroll
    for (int j = 0; j < 8; j++) {
        const int n = j * 8 + 2 * (lane & 3);
        uint32_t hp, lp;
        split_pack2(Oa[j][0] * inv0, Oa[j][1] * inv0, hp, lp);
        *(uint32_t*)(ch + row_off + n) = hp;
        *(uint32_t*)(cl + row_off + n) = lp;
        split_pack2(Oa[j][2] * inv1, Oa[j][3] * inv1, hp, lp);
        *(uint32_t*)(ch + row_off + (size_t)8 * D_ + n) = hp;
        *(uint32_t*)(cl + row_off + (size_t)8 * D_ + n) = lp;
    }
}

// ---------------------------------------------------------------------------
// kernel_launch — graph-capturable, allocation-free
// ---------------------------------------------------------------------------
extern "C" void kernel_launch(void* const* d_in, const int* in_sizes, int n_in,
                              void* d_out, int out_size)
{
    (void)in_sizes; (void)n_in; (void)out_size;
    const float* x     = (const float*)d_in[0];
    const float* w_qkv = (const float*)d_in[1];
    const float* w_out = (const float*)d_in[2];
    float* out = (float*)d_out;

    __nv_bfloat16 *xh, *xl, *wqh, *wql, *woh, *wol, *qh, *ql, *ch, *cl;
    cudaGetSymbolAddress((void**)&xh, g_xh);
    cudaGetSymbolAddress((void**)&xl, g_xl);
    cudaGetSymbolAddress((void**)&wqh, g_wqh);
    cudaGetSymbolAddress((void**)&wql, g_wql);
    cudaGetSymbolAddress((void**)&woh, g_woh);
    cudaGetSymbolAddress((void**)&wol, g_wol);
    cudaGetSymbolAddress((void**)&qh, g_qkvh);
    cudaGetSymbolAddress((void**)&ql, g_qkvl);
    cudaGetSymbolAddress((void**)&ch, g_ch);
    cudaGetSymbolAddress((void**)&cl, g_cl);

    cudaFuncSetAttribute(attn_mma,
                         cudaFuncAttributeMaxDynamicSharedMemorySize, AT_SMEM);

    // splits
    split_bf16<<<(TOK * D_) / 1024, 256>>>(x, xh, xl, (TOK * D_) / 4);
    split_bf16<<<(3 * D_ * D_) / 1024, 256>>>(w_qkv, wqh, wql, (3 * D_ * D_) / 4);
    split_bf16<<<(D_ * D_) / 1024, 256>>>(w_out, woh, wol, (D_ * D_) / 4);

    // 1) QKV projection -> split bf16 head-major qkv
    {
        dim3 grid(3 * D_ / 128, TOK / 128);
        gemm_mma_qkv<<<grid, 512>>>(xh, xl, wqh, wql, qh, ql, D_);
    }
    // 2) tensor-core flash attention -> split bf16 ctx
    {
        dim3 grid(L_ / 128, B_ * H_);
        attn_mma<<<grid, 256, AT_SMEM>>>(qh, ql, ch, cl);
    }
    // 3) output projection
    {
        dim3 grid(D_ / 128, TOK / 128);
        gemm_mma<<<grid, 512>>>(ch, cl, woh, wol, out, D_, D_);
    }
}

// round 7
// speedup vs baseline: 2.3588x; 1.2480x over previous
#include <cuda_runtime.h>
#include <cuda_bf16.h>
#include <cstdint>
#include <cstddef>

// Problem constants
#define B_   2
#define L_   2048
#define D_   1024
#define H_   16
#define HD_  64
#define TOK  (B_ * L_)          // 4096 tokens

// ---------------------------------------------------------------------------
// Scratch (__device__ globals; no cudaMalloc allowed)
// ---------------------------------------------------------------------------
__device__ __align__(16) __nv_bfloat16 g_xh[(size_t)TOK * D_];
__device__ __align__(16) __nv_bfloat16 g_xl[(size_t)TOK * D_];
__device__ __align__(16) __nv_bfloat16 g_wqh[(size_t)3 * D_ * D_];
__device__ __align__(16) __nv_bfloat16 g_wql[(size_t)3 * D_ * D_];
__device__ __align__(16) __nv_bfloat16 g_woh[(size_t)D_ * D_];
__device__ __align__(16) __nv_bfloat16 g_wol[(size_t)D_ * D_];
// head-major split qkv: [part(q/k/v)][b][h][l][64]
__device__ __align__(16) __nv_bfloat16 g_qkvh[(size_t)3 * TOK * D_];
__device__ __align__(16) __nv_bfloat16 g_qkvl[(size_t)3 * TOK * D_];
// attention context, split: [tok][1024]
__device__ __align__(16) __nv_bfloat16 g_ch[(size_t)TOK * D_];
__device__ __align__(16) __nv_bfloat16 g_cl[(size_t)TOK * D_];

// ---------------------------------------------------------------------------
// Helpers
// ---------------------------------------------------------------------------
__device__ __forceinline__ uint32_t smem_u32(const void* p) {
    uint32_t a;
    asm("{ .reg .u64 t; cvta.to.shared.u64 t, %1; cvt.u32.u64 %0, t; }" : "=r"(a) : "l"(p));
    return a;
}

__device__ __forceinline__ void mma16816(float* c, const uint32_t* a, const uint32_t* b) {
    asm volatile("mma.sync.aligned.m16n8k16.row.col.f32.bf16.bf16.f32 "
                 "{%0,%1,%2,%3}, {%4,%5,%6,%7}, {%8,%9}, {%0,%1,%2,%3};"
                 : "+f"(c[0]), "+f"(c[1]), "+f"(c[2]), "+f"(c[3])
                 : "r"(a[0]), "r"(a[1]), "r"(a[2]), "r"(a[3]),
                   "r"(b[0]), "r"(b[1]));
}

__device__ __forceinline__ void ldsm4(uint32_t* r, uint32_t addr) {
    asm volatile("ldmatrix.sync.aligned.m8n8.x4.shared.b16 {%0,%1,%2,%3}, [%4];"
                 : "=r"(r[0]), "=r"(r[1]), "=r"(r[2]), "=r"(r[3]) : "r"(addr));
}
__device__ __forceinline__ void ldsm4t(uint32_t* r, uint32_t addr) {
    asm volatile("ldmatrix.sync.aligned.m8n8.x4.trans.shared.b16 {%0,%1,%2,%3}, [%4];"
                 : "=r"(r[0]), "=r"(r[1]), "=r"(r[2]), "=r"(r[3]) : "r"(addr));
}

__device__ __forceinline__ uint32_t pack_bf(__nv_bfloat16 lo, __nv_bfloat16 hi) {
    return (uint32_t)__bfloat16_as_ushort(lo) | ((uint32_t)__bfloat16_as_ushort(hi) << 16);
}
// split two floats into packed bf16 hi-pair and lo-pair (element0 in low half)
__device__ __forceinline__ void split_pack2(float x, float y, uint32_t& hp, uint32_t& lp) {
    __nv_bfloat16 hx = __float2bfloat16(x), hy = __float2bfloat16(y);
    __nv_bfloat16 lx = __float2bfloat16(x - __bfloat162float(hx));
    __nv_bfloat16 ly = __float2bfloat16(y - __bfloat162float(hy));
    hp = pack_bf(hx, hy);
    lp = pack_bf(lx, ly);
}

#define CP_ASYNC16(dst, src) \
    asm volatile("cp.async.cg.shared.global [%0], [%1], 16;" :: "r"(dst), "l"(src) : "memory")
#define CP_COMMIT() asm volatile("cp.async.commit_group;" ::: "memory")
#define CP_WAIT1()  asm volatile("cp.async.wait_group 1;" ::: "memory")
#define CP_WAIT0()  asm volatile("cp.async.wait_group 0;" ::: "memory")

// ---------------------------------------------------------------------------
// split fp32 -> bf16 hi + lo (for x, w_qkv, w_out)
// ---------------------------------------------------------------------------
__global__ void __launch_bounds__(256) split_bf16(
    const float* __restrict__ in, __nv_bfloat16* __restrict__ hi,
    __nv_bfloat16* __restrict__ lo, int n4)
{
    int i = blockIdx.x * 256 + threadIdx.x;
    if (i >= n4) return;
    float4 v = ((const float4*)in)[i];
    uint32_t h0, l0v, h1, l1v;
    split_pack2(v.x, v.y, h0, l0v);
    split_pack2(v.z, v.w, h1, l1v);
    ((uint32_t*)hi)[i * 2 + 0] = h0;
    ((uint32_t*)hi)[i * 2 + 1] = h1;
    ((uint32_t*)lo)[i * 2 + 0] = l0v;
    ((uint32_t*)lo)[i * 2 + 1] = l1v;
}

// ---------------------------------------------------------------------------
// GEMM: 128x128 CTA tile, BK=32, 512 threads (16 warps 4x4), 3-stage cp.async
// pipeline, ldmatrix fragments. C = (Ah+Al)(Bh+Bl)^T dropping Al*Bl.
// ---------------------------------------------------------------------------
#define SROW 40
#define G_TILE_B  (128 * SROW * 2)        // 10240 B per matrix tile
#define G_STAGE_B (4 * G_TILE_B)          // 40960 B
#define G_SMEM    (3 * G_STAGE_B)         // 122880 B

#define GEMM_BODY(Ah, Al, Bh, Bl, K)                                           \
    extern __shared__ __align__(16) char smemraw[];                            \
    const uint32_t sb = smem_u32(smemraw);                                     \
    const int tid  = threadIdx.x;                                              \
    const int lane = tid & 31;                                                 \
    const int warp = tid >> 5;                                                 \
    const int wm   = warp >> 2;                                                \
    const int wn   = warp & 3;                                                 \
    const int bm   = blockIdx.y * 128;                                         \
    const int bn   = blockIdx.x * 128;                                         \
    const int lrow = tid >> 2;                                                 \
    const int lseg = tid & 3;                                                  \
    const uint32_t dofs = (uint32_t)(lrow * SROW + lseg * 8) * 2;              \
    const size_t gA = (size_t)(bm + lrow) * K + lseg * 8;                      \
    const size_t gB = (size_t)(bn + lrow) * K + lseg * 8;                      \
    float acc[2][4][4];                                                        \
    _Pragma("unroll")                                                          \
    for (int i = 0; i < 2; i++)                                                \
        _Pragma("unroll")                                                      \
        for (int j = 0; j < 4; j++)                                            \
            _Pragma("unroll")                                                  \
            for (int e = 0; e < 4; e++) acc[i][j][e] = 0.0f;                   \
    const int nk = K / 32;                                                     \
    auto load_st = [&](int kt, int st) {                                       \
        const uint32_t base = sb + st * G_STAGE_B + dofs;                      \
        const size_t ko = (size_t)kt * 32;                                     \
        CP_ASYNC16(base + 0 * G_TILE_B, Ah + gA + ko);                         \
        CP_ASYNC16(base + 1 * G_TILE_B, Al + gA + ko);                         \
        CP_ASYNC16(base + 2 * G_TILE_B, Bh + gB + ko);                         \
        CP_ASYNC16(base + 3 * G_TILE_B, Bl + gB + ko);                         \
        CP_COMMIT();                                                           \
    };                                                                         \
    load_st(0, 0);                                                             \
    load_st(1, 1);                                                             \
    for (int kt = 0; kt < nk; kt++) {                                          \
        const int st = kt % 3;                                                 \
        if (kt < nk - 1) { CP_WAIT1(); } else { CP_WAIT0(); }                  \
        __syncthreads();                                                       \
        if (kt + 2 < nk) load_st(kt + 2, (kt + 2) % 3);                        \
        const uint32_t aAh = sb + st * G_STAGE_B;                              \
        const uint32_t aAl = aAh + G_TILE_B;                                   \
        const uint32_t aBh = aAh + 2 * G_TILE_B;                               \
        const uint32_t aBl = aAh + 3 * G_TILE_B;                               \
        _Pragma("unroll")                                                      \
        for (int ks = 0; ks < 32; ks += 16) {                                  \
            const uint32_t a_lro =                                             \
                (uint32_t)((lane & 15) * SROW + (lane >> 4) * 8 + ks) * 2;     \
            const uint32_t b_lro =                                             \
                (uint32_t)((((lane >> 4) << 3) + (lane & 7)) * SROW +          \
                           ((lane >> 3) & 1) * 8 + ks) * 2;                    \
            uint32_t fAh[2][4], fAl[2][4], fB_h[2][4], fB_l[2][4];             \
            _Pragma("unroll")                                                  \
            for (int i = 0; i < 2; i++) {                                      \
                const uint32_t mo = (uint32_t)((wm * 32 + i * 16) * SROW) * 2; \
                ldsm4(fAh[i], aAh + mo + a_lro);                               \
                ldsm4(fAl[i], aAl + mo + a_lro);                               \
            }                                                                  \
            _Pragma("unroll")                                                  \
            for (int jp = 0; jp < 2; jp++) {                                   \
                const uint32_t no = (uint32_t)((wn * 32 + jp * 16) * SROW) * 2;\
                ldsm4(fB_h[jp], aBh + no + b_lro);                             \
                ldsm4(fB_l[jp], aBl + no + b_lro);                             \
            }                                                                  \
            _Pragma("unroll")                                                  \
            for (int i = 0; i < 2; i++)                                        \
                _Pragma("unroll")                                              \
                for (int j = 0; j < 4; j++) {                                  \
                    const uint32_t* bh2 = &fB_h[j >> 1][(j & 1) * 2];          \
                    const uint32_t* bl2 = &fB_l[j >> 1][(j & 1) * 2];          \
                    mma16816(acc[i][j], fAh[i], bh2);                          \
                    mma16816(acc[i][j], fAh[i], bl2);                          \
                    mma16816(acc[i][j], fAl[i], bh2);                          \
                }                                                              \
        }                                                                      \
    }

// Out-proj GEMM: fp32 output, row-major C[M,N]
__global__ void __launch_bounds__(512, 1) gemm_mma(
    const __nv_bfloat16* __restrict__ Ah, const __nv_bfloat16* __restrict__ Al,
    const __nv_bfloat16* __restrict__ Bh, const __nv_bfloat16* __restrict__ Bl,
    float* __restrict__ C, int N, int K)
{
    GEMM_BODY(Ah, Al, Bh, Bl, K)
    #pragma unroll
    for (int i = 0; i < 2; i++) {
        const int m = bm + wm * 32 + i * 16 + (lane >> 2);
        #pragma unroll
        for (int j = 0; j < 4; j++) {
            const int n = bn + wn * 32 + j * 8 + (lane & 3) * 2;
            *(float2*)(C + (size_t)m * N + n)       = make_float2(acc[i][j][0], acc[i][j][1]);
            *(float2*)(C + (size_t)(m + 8) * N + n) = make_float2(acc[i][j][2], acc[i][j][3]);
        }
    }
}

// QKV GEMM: writes split bf16 head-major qkv [part][b][h][l][64]
__global__ void __launch_bounds__(512, 1) gemm_mma_qkv(
    const __nv_bfloat16* __restrict__ Ah, const __nv_bfloat16* __restrict__ Al,
    const __nv_bfloat16* __restrict__ Bh, const __nv_bfloat16* __restrict__ Bl,
    __nv_bfloat16* __restrict__ Qh, __nv_bfloat16* __restrict__ Ql, int K)
{
    GEMM_BODY(Ah, Al, Bh, Bl, K)
    #pragma unroll
    for (int i = 0; i < 2; i++) {
        const int m = bm + wm * 32 + i * 16 + (lane >> 2);   // token
        const int bb = m >> 11, ll = m & 2047;
        #pragma unroll
        for (int j = 0; j < 4; j++) {
            const int n = bn + wn * 32 + j * 8 + (lane & 3) * 2;
            const int part = n >> 10, rem = n & 1023, hh = rem >> 6, dd = rem & 63;
            const size_t off = (((size_t)(part * B_ + bb) * H_ + hh) * L_ + ll) * HD_ + dd;
            uint32_t hp, lp;
            split_pack2(acc[i][j][0], acc[i][j][1], hp, lp);
            *(uint32_t*)(Qh + off) = hp;
            *(uint32_t*)(Ql + off) = lp;
            split_pack2(acc[i][j][2], acc[i][j][3], hp, lp);
            *(uint32_t*)(Qh + off + (size_t)8 * HD_) = hp;
            *(uint32_t*)(Ql + off + (size_t)8 * HD_) = lp;
        }
    }
}

// ---------------------------------------------------------------------------
// Tensor-core causal flash attention (ldmatrix fragments).
// Block = (b,h) x 128-row Q tile. 256 threads, 8 warps; warp owns 16 rows.
// K/V tiles (64 keys) double-buffered via cp.async.
// ---------------------------------------------------------------------------
#define KSTR  72                         // smem row stride (bf16 elems)
#define AT_TILE  (64 * KSTR * 2)         // 9216 B per matrix tile
#define AT_STAGE (4 * AT_TILE)           // Kh,Kl,Vh,Vl
#define AT_SMEM  (2 * AT_STAGE)          // 73728 B

__global__ void __launch_bounds__(256, 2) attn_mma(
    const __nv_bfloat16* __restrict__ qkvh,
    const __nv_bfloat16* __restrict__ qkvl,
    __nv_bfloat16* __restrict__ ch, __nv_bfloat16* __restrict__ cl)
{
    extern __shared__ __align__(16) char smem[];
    const uint32_t sb = smem_u32(smem);
    const int tid = threadIdx.x, lane = tid & 31, warp = tid >> 5;
    const int qt = (int)gridDim.x - 1 - (int)blockIdx.x;   // long blocks first
    const int bh = blockIdx.y, b = bh >> 4, h = bh & 15;
    const int q0 = qt * 128;
    const size_t PART = (size_t)TOK * D_;
    const size_t headoff = (size_t)bh * L_ * HD_;
    const __nv_bfloat16* Qh = qkvh + headoff;
    const __nv_bfloat16* Ql = qkvl + headoff;
    const __nv_bfloat16* Kh = qkvh + PART + headoff;
    const __nv_bfloat16* Kl = qkvl + PART + headoff;
    const __nv_bfloat16* Vh = qkvh + 2 * PART + headoff;
    const __nv_bfloat16* Vl = qkvl + 2 * PART + headoff;

    const int r0 = q0 + warp * 16 + (lane >> 2);   // this lane's first row

    // Q fragments (hi/lo) from global, a-frag m16k16 layout, 4 k-steps
    uint32_t qfh[4][4], qfl[4][4];
    {
        const __nv_bfloat16* p0  = Qh + (size_t)r0 * HD_;
        const __nv_bfloat16* p8  = p0 + 8 * HD_;
        const __nv_bfloat16* p0l = Ql + (size_t)r0 * HD_;
        const __nv_bfloat16* p8l = p0l + 8 * HD_;
        #pragma unroll
        for (int t = 0; t < 4; t++) {
            const int d0 = t * 16 + 2 * (lane & 3);
            qfh[t][0] = *(const uint32_t*)(p0 + d0);
            qfh[t][1] = *(const uint32_t*)(p8 + d0);
            qfh[t][2] = *(const uint32_t*)(p0 + d0 + 8);
            qfh[t][3] = *(const uint32_t*)(p8 + d0 + 8);
            qfl[t][0] = *(const uint32_t*)(p0l + d0);
            qfl[t][1] = *(const uint32_t*)(p8l + d0);
            qfl[t][2] = *(const uint32_t*)(p0l + d0 + 8);
            qfl[t][3] = *(const uint32_t*)(p8l + d0 + 8);
        }
    }

    float Oa[8][4];
    #pragma unroll
    for (int j = 0; j < 8; j++)
        #pragma unroll
        for (int e = 0; e < 4; e++) Oa[j][e] = 0.0f;
    float m0 = -1e30f, m1 = -1e30f, l0 = 0.0f, l1 = 0.0f;

    const int ntiles = 2 * qt + 2;

    auto load_tile = [&](int kt, int stage) {
        const uint32_t dstbase = sb + stage * AT_STAGE;
        #pragma unroll
        for (int i = 0; i < 2; i++) {
            const int rem = tid + i * 256;          // 0..511
            const int row = rem >> 3, dch = rem & 7;
            const size_t g = (size_t)(kt * 64 + row) * HD_ + dch * 8;
            const uint32_t dof = dstbase + row * (KSTR * 2) + dch * 16;
            CP_ASYNC16(dof + 0 * AT_TILE, Kh + g);
            CP_ASYNC16(dof + 1 * AT_TILE, Kl + g);
            CP_ASYNC16(dof + 2 * AT_TILE, Vh + g);
            CP_ASYNC16(dof + 3 * AT_TILE, Vl + g);
        }
        CP_COMMIT();
    };

    load_tile(0, 0);

    for (int kt = 0; kt < ntiles; kt++) {
        const int stage = kt & 1;
        if (kt + 1 < ntiles) { load_tile(kt + 1, (kt + 1) & 1); CP_WAIT1(); }
        else                 { CP_WAIT0(); }
        __syncthreads();

        const int k0 = kt * 64;
        if (k0 <= q0 + warp * 16 + 15) {          // warp-uniform: any work?
            const uint32_t kbh = sb + stage * AT_STAGE;
            const uint32_t kbl = kbh + AT_TILE;
            const uint32_t vbh = kbh + 2 * AT_TILE;
            const uint32_t vbl = kbh + 3 * AT_TILE;

            // ---- S = Q K^T ----
            float Sa[8][4];
            #pragma unroll
            for (int j = 0; j < 8; j++)
                #pragma unroll
                for (int e = 0; e < 4; e++) Sa[j][e] = 0.0f;

            const uint32_t k_lro =
                (uint32_t)((((lane >> 4) << 3) + (lane & 7)) * KSTR +
                           ((lane >> 3) & 1) * 8) * 2;
            #pragma unroll
            for (int jp = 0; jp < 4; jp++) {
                const uint32_t no = (uint32_t)(jp * 16 * KSTR) * 2;
                #pragma unroll
                for (int t = 0; t < 4; t++) {
                    const uint32_t co = (uint32_t)(t * 16) * 2;
                    uint32_t kb4h[4], kb4l[4];
                    ldsm4(kb4h, kbh + no + k_lro + co);
                    ldsm4(kb4l, kbl + no + k_lro + co);
                    mma16816(Sa[2 * jp],     qfh[t], &kb4h[0]);
                    mma16816(Sa[2 * jp],     qfh[t], &kb4l[0]);
                    mma16816(Sa[2 * jp],     qfl[t], &kb4h[0]);
                    mma16816(Sa[2 * jp + 1], qfh[t], &kb4h[2]);
                    mma16816(Sa[2 * jp + 1], qfh[t], &kb4l[2]);
                    mma16816(Sa[2 * jp + 1], qfl[t], &kb4h[2]);
                }
            }

            // ---- scale + causal mask ----
            const bool needmask = (k0 + 63 > q0 + warp * 16);
            #pragma unroll
            for (int j = 0; j < 8; j++) {
                #pragma unroll
                for (int e = 0; e < 4; e++) Sa[j][e] *= 0.125f;
                if (needmask) {
                    const int key0 = k0 + j * 8 + 2 * (lane & 3);
                    if (key0     > r0)     Sa[j][0] = -1e30f;
                    if (key0 + 1 > r0)     Sa[j][1] = -1e30f;
                    if (key0     > r0 + 8) Sa[j][2] = -1e30f;
                    if (key0 + 1 > r0 + 8) Sa[j][3] = -1e30f;
                }
            }

            // ---- online softmax (2 rows per lane, quad reductions) ----
            float mx0 = -1e30f, mx1 = -1e30f;
            #pragma unroll
            for (int j = 0; j < 8; j++) {
                mx0 = fmaxf(mx0, fmaxf(Sa[j][0], Sa[j][1]));
                mx1 = fmaxf(mx1, fmaxf(Sa[j][2], Sa[j][3]));
            }
            mx0 = fmaxf(mx0, __shfl_xor_sync(0xffffffffu, mx0, 1));
            mx0 = fmaxf(mx0, __shfl_xor_sync(0xffffffffu, mx0, 2));
            mx1 = fmaxf(mx1, __shfl_xor_sync(0xffffffffu, mx1, 1));
            mx1 = fmaxf(mx1, __shfl_xor_sync(0xffffffffu, mx1, 2));
            const float mn0 = fmaxf(m0, mx0), mn1 = fmaxf(m1, mx1);
            const float a0 = __expf(m0 - mn0), a1 = __expf(m1 - mn1);
            m0 = mn0; m1 = mn1;
            float rs0 = 0.0f, rs1 = 0.0f;
            #pragma unroll
            for (int j = 0; j < 8; j++) {
                Sa[j][0] = __expf(Sa[j][0] - mn0); rs0 += Sa[j][0];
                Sa[j][1] = __expf(Sa[j][1] - mn0); rs0 += Sa[j][1];
                Sa[j][2] = __expf(Sa[j][2] - mn1); rs1 += Sa[j][2];
                Sa[j][3] = __expf(Sa[j][3] - mn1); rs1 += Sa[j][3];
            }
            rs0 += __shfl_xor_sync(0xffffffffu, rs0, 1);
            rs0 += __shfl_xor_sync(0xffffffffu, rs0, 2);
            rs1 += __shfl_xor_sync(0xffffffffu, rs1, 1);
            rs1 += __shfl_xor_sync(0xffffffffu, rs1, 2);
            l0 = l0 * a0 + rs0;
            l1 = l1 * a1 + rs1;
            #pragma unroll
            for (int j = 0; j < 8; j++) {
                Oa[j][0] *= a0; Oa[j][1] *= a0;
                Oa[j][2] *= a1; Oa[j][3] *= a1;
            }

            // ---- O += P V (P from accumulators; V frags via ldmatrix.trans) --
            const uint32_t v_lro =
                (uint32_t)((((lane >> 3) & 1) * 8 + (lane & 7)) * KSTR +
                           (lane >> 4) * 8) * 2;
            #pragma unroll
            for (int t = 0; t < 4; t++) {
                uint32_t ah[4], al[4];
                split_pack2(Sa[2 * t][0],     Sa[2 * t][1],     ah[0], al[0]);
                split_pack2(Sa[2 * t][2],     Sa[2 * t][3],     ah[1], al[1]);
                split_pack2(Sa[2 * t + 1][0], Sa[2 * t + 1][1], ah[2], al[2]);
                split_pack2(Sa[2 * t + 1][2], Sa[2 * t + 1][3], ah[3], al[3]);
                const uint32_t ro = (uint32_t)(t * 16 * KSTR) * 2;
                #pragma unroll
                for (int jp = 0; jp < 4; jp++) {
                    const uint32_t co = (uint32_t)(jp * 16) * 2;
                    uint32_t vh4[4], vl4[4];
                    ldsm4t(vh4, vbh + ro + v_lro + co);
                    ldsm4t(vl4, vbl + ro + v_lro + co);
                    mma16816(Oa[2 * jp],     ah, &vh4[0]);
                    mma16816(Oa[2 * jp],     ah, &vl4[0]);
                    mma16816(Oa[2 * jp],     al, &vh4[0]);
                    mma16816(Oa[2 * jp + 1], ah, &vh4[2]);
                    mma16816(Oa[2 * jp + 1], ah, &vl4[2]);
                    mma16816(Oa[2 * jp + 1], al, &vh4[2]);
                }
            }
        }
        __syncthreads();
    }

    // ---- finalize: write ctx hi/lo bf16 [tok][1024] ----
    const float inv0 = 1.0f / l0, inv1 = 1.0f / l1;
    const size_t row_off = (size_t)(b * L_ + r0) * D_ + h * 64;
    #pragma unroll
    for (int j = 0; j < 8; j++) {
        const int n = j * 8 + 2 * (lane & 3);
        uint32_t hp, lp;
        split_pack2(Oa[j][0] * inv0, Oa[j][1] * inv0, hp, lp);
        *(uint32_t*)(ch + row_off + n) = hp;
        *(uint32_t*)(cl + row_off + n) = lp;
        split_pack2(Oa[j][2] * inv1, Oa[j][3] * inv1, hp, lp);
        *(uint32_t*)(ch + row_off + (size_t)8 * D_ + n) = hp;
        *(uint32_t*)(cl + row_off + (size_t)8 * D_ + n) = lp;
    }
}

// ---------------------------------------------------------------------------
// kernel_launch — graph-capturable, allocation-free
// ---------------------------------------------------------------------------
extern "C" void kernel_launch(void* const* d_in, const int* in_sizes, int n_in,
                              void* d_out, int out_size)
{
    (void)in_sizes; (void)n_in; (void)out_size;
    const float* x     = (const float*)d_in[0];
    const float* w_qkv = (const float*)d_in[1];
    const float* w_out = (const float*)d_in[2];
    float* out = (float*)d_out;

    __nv_bfloat16 *xh, *xl, *wqh, *wql, *woh, *wol, *qh, *ql, *ch, *cl;
    cudaGetSymbolAddress((void**)&xh, g_xh);
    cudaGetSymbolAddress((void**)&xl, g_xl);
    cudaGetSymbolAddress((void**)&wqh, g_wqh);
    cudaGetSymbolAddress((void**)&wql, g_wql);
    cudaGetSymbolAddress((void**)&woh, g_woh);
    cudaGetSymbolAddress((void**)&wol, g_wol);
    cudaGetSymbolAddress((void**)&qh, g_qkvh);
    cudaGetSymbolAddress((void**)&ql, g_qkvl);
    cudaGetSymbolAddress((void**)&ch, g_ch);
    cudaGetSymbolAddress((void**)&cl, g_cl);

    cudaFuncSetAttribute(attn_mma,
                         cudaFuncAttributeMaxDynamicSharedMemorySize, AT_SMEM);
    cudaFuncSetAttribute(gemm_mma,
                         cudaFuncAttributeMaxDynamicSharedMemorySize, G_SMEM);
    cudaFuncSetAttribute(gemm_mma_qkv,
                         cudaFuncAttributeMaxDynamicSharedMemorySize, G_SMEM);

    // splits
    split_bf16<<<(TOK * D_) / 1024, 256>>>(x, xh, xl, (TOK * D_) / 4);
    split_bf16<<<(3 * D_ * D_) / 1024, 256>>>(w_qkv, wqh, wql, (3 * D_ * D_) / 4);
    split_bf16<<<(D_ * D_) / 1024, 256>>>(w_out, woh, wol, (D_ * D_) / 4);

    // 1) QKV projection -> split bf16 head-major qkv
    {
        dim3 grid(3 * D_ / 128, TOK / 128);
        gemm_mma_qkv<<<grid, 512, G_SMEM>>>(xh, xl, wqh, wql, qh, ql, D_);
    }
    // 2) tensor-core flash attention -> split bf16 ctx
    {
        dim3 grid(L_ / 128, B_ * H_);
        attn_mma<<<grid, 256, AT_SMEM>>>(qh, ql, ch, cl);
    }
    // 3) output projection
    {
        dim3 grid(D_ / 128, TOK / 128);
        gemm_mma<<<grid, 512, G_SMEM>>>(ch, cl, woh, wol, out, D_, D_);
    }
}